// round 8
// baseline (speedup 1.0000x reference)
#include <cuda_runtime.h>
#include <cuda_bf16.h>

// WeightAndSum: out[s, :] = sum_{r in segment s} feats[r,:] * sigmoid(dot(feats[r,:], w) + b)
// N = 2,000,000 rows, D = 128, B = 65536 segments, segment_ids sorted ascending.
//
// Plan (zero atomics, zero memset):
//  1) offs_kernel (vectorized): g_offs[b] = first row of segment b, g_offs[B]=N.
//  2) was_kernel: warp per segment (branchless hot loop, exclusive ownership,
//     exactly one float4 store per lane per segment — empties store zeros).
//     Distance-2 prefetch with only TWO register buffers: the load of group
//     g+2 is issued at the END of iteration g into the buffer g just freed
//     (its registers are last read by the accumulate FFMAs). Unrolled-by-2
//     A/B ping-pong avoids buffer-swap MOVs. Cover per load ~= one full
//     iteration instead of one compute phase.

#define D_DIM 128
#define THREADS 256
#define WARPS (THREADS / 32)
#define MAX_B 65536

__device__ int g_offs[MAX_B + 1];

__global__ __launch_bounds__(256) void offs_kernel(
    const int* __restrict__ seg, int N, int B)
{
    const int i    = blockIdx.x * blockDim.x + threadIdx.x;
    const int base = i * 4;
    if (base >= N) return;

    const int prev = (base == 0) ? -1 : __ldg(seg + base - 1);

    int ids[4];
    if (base + 4 <= N) {
        const int4 v = *reinterpret_cast<const int4*>(seg + base);
        ids[0] = v.x; ids[1] = v.y; ids[2] = v.z; ids[3] = v.w;
    } else {
#pragma unroll
        for (int k = 0; k < 4; ++k)
            ids[k] = (base + k < N) ? __ldg(seg + base + k) : 0;
    }

    int p = prev;
#pragma unroll
    for (int k = 0; k < 4; ++k) {
        if (base + k >= N) break;
        const int s = ids[k];
        for (int bb = p + 1; bb <= s; ++bb) g_offs[bb] = base + k;
        p = s;
        if (base + k == N - 1)
            for (int bb = s + 1; bb <= B; ++bb) g_offs[bb] = N;
    }
}

__global__ __launch_bounds__(THREADS) void was_kernel(
    const float* __restrict__ feats,
    const float* __restrict__ w,
    const float* __restrict__ b,
    float*       __restrict__ out,
    int B)
{
    const int wid  = threadIdx.x >> 5;
    const int lane = threadIdx.x & 31;
    const int s    = blockIdx.x * WARPS + wid;
    if (s >= B) return;

    const int start = __ldg(&g_offs[s]);
    const int end   = __ldg(&g_offs[s + 1]);

    const float4 wv  = reinterpret_cast<const float4*>(w)[lane];
    const float bias = __ldg(b);

    float4 acc = make_float4(0.f, 0.f, 0.f, 0.f);

    const int G = (end - start) >> 2;  // full 4-row groups

    // load 4-row group gi into the given float4 buffer set
#define LOADG(D0, D1, D2, D3, gi)                                            \
    do {                                                                     \
        const float4* bp = reinterpret_cast<const float4*>(feats)            \
                         + (size_t)(start + (gi) * 4) * (D_DIM / 4) + lane;  \
        D0 = __ldcs(bp);                                                     \
        D1 = __ldcs(bp + (D_DIM / 4));                                       \
        D2 = __ldcs(bp + 2 * (D_DIM / 4));                                   \
        D3 = __ldcs(bp + 3 * (D_DIM / 4));                                   \
    } while (0)

    // consume one group, then refill the SAME buffer with group gi+2
#define BODY(F0, F1, F2, F3, gi)                                             \
    do {                                                                     \
        float p0 = F0.x * wv.x + F0.y * wv.y + F0.z * wv.z + F0.w * wv.w;    \
        float p1 = F1.x * wv.x + F1.y * wv.y + F1.z * wv.z + F1.w * wv.w;    \
        float p2 = F2.x * wv.x + F2.y * wv.y + F2.z * wv.z + F2.w * wv.w;    \
        float p3 = F3.x * wv.x + F3.y * wv.y + F3.z * wv.z + F3.w * wv.w;    \
        _Pragma("unroll")                                                    \
        for (int o = 16; o > 0; o >>= 1) {                                   \
            p0 += __shfl_xor_sync(0xffffffffu, p0, o);                       \
            p1 += __shfl_xor_sync(0xffffffffu, p1, o);                       \
            p2 += __shfl_xor_sync(0xffffffffu, p2, o);                       \
            p3 += __shfl_xor_sync(0xffffffffu, p3, o);                       \
        }                                                                    \
        const float g0 = 1.0f / (1.0f + __expf(-(p0 + bias)));               \
        const float g1 = 1.0f / (1.0f + __expf(-(p1 + bias)));               \
        const float g2 = 1.0f / (1.0f + __expf(-(p2 + bias)));               \
        const float g3 = 1.0f / (1.0f + __expf(-(p3 + bias)));               \
        acc.x += F0.x * g0 + F1.x * g1 + F2.x * g2 + F3.x * g3;              \
        acc.y += F0.y * g0 + F1.y * g1 + F2.y * g2 + F3.y * g3;              \
        acc.z += F0.z * g0 + F1.z * g1 + F2.z * g2 + F3.z * g3;              \
        acc.w += F0.w * g0 + F1.w * g1 + F2.w * g2 + F3.w * g3;              \
        if ((gi) + 2 < G) LOADG(F0, F1, F2, F3, (gi) + 2);                   \
    } while (0)

    float4 A0, A1, A2, A3, B0, B1, B2, B3;
    if (G > 0) LOADG(A0, A1, A2, A3, 0);
    if (G > 1) LOADG(B0, B1, B2, B3, 1);

    int g = 0;
    while (g < G) {
        BODY(A0, A1, A2, A3, g);          // even groups in A
        ++g;
        if (g >= G) break;
        BODY(B0, B1, B2, B3, g);          // odd groups in B
        ++g;
    }
#undef BODY
#undef LOADG

    // tail rows (0..3)
    for (int r = start + G * 4; r < end; ++r) {
        const float4 f =
            reinterpret_cast<const float4*>(feats)[(size_t)r * (D_DIM / 4) + lane];
        float p = f.x * wv.x + f.y * wv.y + f.z * wv.z + f.w * wv.w;
#pragma unroll
        for (int o = 16; o > 0; o >>= 1) p += __shfl_xor_sync(0xffffffffu, p, o);
        const float gg = 1.0f / (1.0f + __expf(-(p + bias)));
        acc.x += f.x * gg;
        acc.y += f.y * gg;
        acc.z += f.z * gg;
        acc.w += f.w * gg;
    }

    // exclusive owner: single plain store (zeros for empty segments)
    *reinterpret_cast<float4*>(out + (size_t)s * D_DIM + lane * 4) = acc;
}

extern "C" void kernel_launch(void* const* d_in, const int* in_sizes, int n_in,
                              void* d_out, int out_size)
{
    const float* feats = (const float*)d_in[0];
    const int*   seg   = (const int*)d_in[1];
    const float* w     = (const float*)d_in[2];
    const float* b     = (const float*)d_in[3];
    float*       out   = (float*)d_out;

    const int N = in_sizes[1];            // rows
    const int B = out_size / D_DIM;       // segments (65536)

    const int groups = (N + 3) / 4;
    offs_kernel<<<(groups + 255) / 256, 256>>>(seg, N, B);

    const int blocks = (B + WARPS - 1) / WARPS;
    was_kernel<<<blocks, THREADS>>>(feats, w, b, out, B);
}

// round 9
// speedup vs baseline: 1.2200x; 1.2200x over previous
#include <cuda_runtime.h>
#include <cuda_bf16.h>

// WeightAndSum: out[s, :] = sum_{r in segment s} feats[r,:] * sigmoid(dot(feats[r,:], w) + b)
// N = 2,000,000 rows, D = 128, B = 65536 segments, segment_ids sorted ascending.
//
// Two-kernel plan, zero atomics, zero memset:
//  1) offs_kernel (vectorized int4): g_offs[b] = first row of segment b,
//     g_offs[B] = N, handling empty segments.
//  2) was_kernel (R6 shape — proven best): warp per segment, exclusive
//     ownership. 4-row groups, register double-buffered with loads batched
//     UNCONDITIONALLY at loop top (single bottom branch) — this is the shape
//     ptxas schedules well; all variants entangling control flow with the
//     buffers (R7 ADVANCE_TO, R8 end-of-body conditional prefetch) regressed.
//     One plain float4 store per lane per segment; empties store zeros.

#define D_DIM 128
#define THREADS 256
#define WARPS (THREADS / 32)
#define MAX_B 65536

__device__ int g_offs[MAX_B + 1];

__global__ __launch_bounds__(256) void offs_kernel(
    const int* __restrict__ seg, int N, int B)
{
    const int i    = blockIdx.x * blockDim.x + threadIdx.x;
    const int base = i * 4;
    if (base >= N) return;

    const int prev = (base == 0) ? -1 : __ldg(seg + base - 1);

    int ids[4];
    if (base + 4 <= N) {
        const int4 v = *reinterpret_cast<const int4*>(seg + base);
        ids[0] = v.x; ids[1] = v.y; ids[2] = v.z; ids[3] = v.w;
    } else {
#pragma unroll
        for (int k = 0; k < 4; ++k)
            ids[k] = (base + k < N) ? __ldg(seg + base + k) : 0;
    }

    int p = prev;
#pragma unroll
    for (int k = 0; k < 4; ++k) {
        if (base + k >= N) break;
        const int s = ids[k];
        for (int bb = p + 1; bb <= s; ++bb) g_offs[bb] = base + k;
        p = s;
        if (base + k == N - 1)
            for (int bb = s + 1; bb <= B; ++bb) g_offs[bb] = N;
    }
}

__global__ __launch_bounds__(THREADS) void was_kernel(
    const float* __restrict__ feats,
    const float* __restrict__ w,
    const float* __restrict__ b,
    float*       __restrict__ out,
    int B)
{
    const int wid  = threadIdx.x >> 5;
    const int lane = threadIdx.x & 31;
    const int s    = blockIdx.x * WARPS + wid;
    if (s >= B) return;

    const int start = __ldg(&g_offs[s]);
    const int end   = __ldg(&g_offs[s + 1]);

    const float4 wv  = reinterpret_cast<const float4*>(w)[lane];
    const float bias = __ldg(b);

    float4 acc = make_float4(0.f, 0.f, 0.f, 0.f);

    int r = start;
    const int stop = start + ((end - start) & ~3);  // full 4-row groups

    if (r < stop) {
        // ---- prologue: load group 0 ----
        const float4* base =
            reinterpret_cast<const float4*>(feats) + (size_t)r * (D_DIM / 4) + lane;
        float4 f0 = __ldcs(base);
        float4 f1 = __ldcs(base + (D_DIM / 4));
        float4 f2 = __ldcs(base + 2 * (D_DIM / 4));
        float4 f3 = __ldcs(base + 3 * (D_DIM / 4));

        for (;;) {
            const int rn    = r + 4;
            const bool more = (rn < stop);

            // ---- prefetch next group before current chain ----
            float4 f0n, f1n, f2n, f3n;
            if (more) {
                const float4* bn =
                    reinterpret_cast<const float4*>(feats) + (size_t)rn * (D_DIM / 4) + lane;
                f0n = __ldcs(bn);
                f1n = __ldcs(bn + (D_DIM / 4));
                f2n = __ldcs(bn + 2 * (D_DIM / 4));
                f3n = __ldcs(bn + 3 * (D_DIM / 4));
            }

            // ---- 4 per-lane partial dots, 4 parallel butterflies ----
            float p0 = f0.x * wv.x + f0.y * wv.y + f0.z * wv.z + f0.w * wv.w;
            float p1 = f1.x * wv.x + f1.y * wv.y + f1.z * wv.z + f1.w * wv.w;
            float p2 = f2.x * wv.x + f2.y * wv.y + f2.z * wv.z + f2.w * wv.w;
            float p3 = f3.x * wv.x + f3.y * wv.y + f3.z * wv.z + f3.w * wv.w;

#pragma unroll
            for (int o = 16; o > 0; o >>= 1) {
                p0 += __shfl_xor_sync(0xffffffffu, p0, o);
                p1 += __shfl_xor_sync(0xffffffffu, p1, o);
                p2 += __shfl_xor_sync(0xffffffffu, p2, o);
                p3 += __shfl_xor_sync(0xffffffffu, p3, o);
            }

            const float g0 = 1.0f / (1.0f + __expf(-(p0 + bias)));
            const float g1 = 1.0f / (1.0f + __expf(-(p1 + bias)));
            const float g2 = 1.0f / (1.0f + __expf(-(p2 + bias)));
            const float g3 = 1.0f / (1.0f + __expf(-(p3 + bias)));

            // ---- branchless accumulate (single owner: no flush logic) ----
            acc.x += f0.x * g0 + f1.x * g1 + f2.x * g2 + f3.x * g3;
            acc.y += f0.y * g0 + f1.y * g1 + f2.y * g2 + f3.y * g3;
            acc.z += f0.z * g0 + f1.z * g1 + f2.z * g2 + f3.z * g3;
            acc.w += f0.w * g0 + f1.w * g1 + f2.w * g2 + f3.w * g3;

            if (!more) { r = rn; break; }
            f0 = f0n; f1 = f1n; f2 = f2n; f3 = f3n;
            r = rn;
        }
    }

    // ---- tail rows (0..3) ----
    for (; r < end; ++r) {
        const float4 f =
            reinterpret_cast<const float4*>(feats)[(size_t)r * (D_DIM / 4) + lane];
        float p = f.x * wv.x + f.y * wv.y + f.z * wv.z + f.w * wv.w;
#pragma unroll
        for (int o = 16; o > 0; o >>= 1) p += __shfl_xor_sync(0xffffffffu, p, o);
        const float g = 1.0f / (1.0f + __expf(-(p + bias)));
        acc.x += f.x * g;
        acc.y += f.y * g;
        acc.z += f.z * g;
        acc.w += f.w * g;
    }

    // ---- exclusive owner: single plain store (zeros for empty segments) ----
    *reinterpret_cast<float4*>(out + (size_t)s * D_DIM + lane * 4) = acc;
}

extern "C" void kernel_launch(void* const* d_in, const int* in_sizes, int n_in,
                              void* d_out, int out_size)
{
    const float* feats = (const float*)d_in[0];
    const int*   seg   = (const int*)d_in[1];
    const float* w     = (const float*)d_in[2];
    const float* b     = (const float*)d_in[3];
    float*       out   = (float*)d_out;

    const int N = in_sizes[1];            // rows
    const int B = out_size / D_DIM;       // segments (65536)

    const int groups = (N + 3) / 4;
    offs_kernel<<<(groups + 255) / 256, 256>>>(seg, N, B);

    const int blocks = (B + WARPS - 1) / WARPS;
    was_kernel<<<blocks, THREADS>>>(feats, w, b, out, B);
}

// round 10
// speedup vs baseline: 1.2502x; 1.0248x over previous
#include <cuda_runtime.h>
#include <cuda_bf16.h>

// WeightAndSum: out[s, :] = sum_{r in segment s} feats[r,:] * sigmoid(dot(feats[r,:], w) + b)
// N = 2,000,000 rows, D = 128, B = 65536 segments, segment_ids sorted ascending.
//
// Two-kernel plan, zero atomics, zero memset:
//  1) offs_kernel (vectorized int4, shuffle for prev): g_offs[b] = first row
//     of segment b, g_offs[B] = N, handling empty segments.
//  2) was_kernel (R6 shape — proven best): warp per segment, exclusive
//     ownership, branchless double-buffered 4-row pipeline, one float4 store
//     per lane per segment (empties store zeros). Launched with PDL
//     (programmatic stream serialization) so its setup overlaps offs_kernel's
//     tail; cudaGridDependencySynchronize() guards the first g_offs read.
//     THREADS=128 for finer block-tail granularity.

#define D_DIM 128
#define THREADS 128
#define WARPS (THREADS / 32)
#define MAX_B 65536

__device__ int g_offs[MAX_B + 1];

__global__ __launch_bounds__(256) void offs_kernel(
    const int* __restrict__ seg, int N, int B)
{
    const int i    = blockIdx.x * blockDim.x + threadIdx.x;
    const int base = i * 4;
    const int lane = threadIdx.x & 31;

    int ids[4] = {0, 0, 0, 0};
    const bool active = (base < N);
    if (active) {
        if (base + 4 <= N) {
            const int4 v = *reinterpret_cast<const int4*>(seg + base);
            ids[0] = v.x; ids[1] = v.y; ids[2] = v.z; ids[3] = v.w;
        } else {
#pragma unroll
            for (int k = 0; k < 4; ++k)
                ids[k] = (base + k < N) ? __ldg(seg + base + k) : 0;
        }
    }

    // prev = seg[base-1]: lane l-1 holds it as ids[3]; warp-edge lanes load it
    const int up = __shfl_up_sync(0xffffffffu, ids[3], 1);
    int prev;
    if (lane == 0)
        prev = (base == 0) ? -1 : __ldg(seg + base - 1);
    else
        prev = up;

    if (!active) return;

    int p = prev;
#pragma unroll
    for (int k = 0; k < 4; ++k) {
        if (base + k >= N) break;
        const int s = ids[k];
        for (int bb = p + 1; bb <= s; ++bb) g_offs[bb] = base + k;
        p = s;
        if (base + k == N - 1)
            for (int bb = s + 1; bb <= B; ++bb) g_offs[bb] = N;
    }
}

__global__ __launch_bounds__(THREADS) void was_kernel(
    const float* __restrict__ feats,
    const float* __restrict__ w,
    const float* __restrict__ b,
    float*       __restrict__ out,
    int B)
{
    const int wid  = threadIdx.x >> 5;
    const int lane = threadIdx.x & 31;
    const int s    = blockIdx.x * WARPS + wid;

    // setup that does NOT depend on g_offs — overlaps offs_kernel via PDL
    const float4 wv  = reinterpret_cast<const float4*>(w)[lane];
    const float bias = __ldg(b);

#if __CUDA_ARCH__ >= 900
    cudaGridDependencySynchronize();
#endif

    if (s >= B) return;

    const int start = __ldg(&g_offs[s]);
    const int end   = __ldg(&g_offs[s + 1]);

    float4 acc = make_float4(0.f, 0.f, 0.f, 0.f);

    int r = start;
    const int stop = start + ((end - start) & ~3);  // full 4-row groups

    if (r < stop) {
        // ---- prologue: load group 0 ----
        const float4* base =
            reinterpret_cast<const float4*>(feats) + (size_t)r * (D_DIM / 4) + lane;
        float4 f0 = __ldcs(base);
        float4 f1 = __ldcs(base + (D_DIM / 4));
        float4 f2 = __ldcs(base + 2 * (D_DIM / 4));
        float4 f3 = __ldcs(base + 3 * (D_DIM / 4));

        for (;;) {
            const int rn    = r + 4;
            const bool more = (rn < stop);

            // ---- prefetch next group before current chain ----
            float4 f0n, f1n, f2n, f3n;
            if (more) {
                const float4* bn =
                    reinterpret_cast<const float4*>(feats) + (size_t)rn * (D_DIM / 4) + lane;
                f0n = __ldcs(bn);
                f1n = __ldcs(bn + (D_DIM / 4));
                f2n = __ldcs(bn + 2 * (D_DIM / 4));
                f3n = __ldcs(bn + 3 * (D_DIM / 4));
            }

            // ---- 4 per-lane partial dots, 4 parallel butterflies ----
            float p0 = f0.x * wv.x + f0.y * wv.y + f0.z * wv.z + f0.w * wv.w;
            float p1 = f1.x * wv.x + f1.y * wv.y + f1.z * wv.z + f1.w * wv.w;
            float p2 = f2.x * wv.x + f2.y * wv.y + f2.z * wv.z + f2.w * wv.w;
            float p3 = f3.x * wv.x + f3.y * wv.y + f3.z * wv.z + f3.w * wv.w;

#pragma unroll
            for (int o = 16; o > 0; o >>= 1) {
                p0 += __shfl_xor_sync(0xffffffffu, p0, o);
                p1 += __shfl_xor_sync(0xffffffffu, p1, o);
                p2 += __shfl_xor_sync(0xffffffffu, p2, o);
                p3 += __shfl_xor_sync(0xffffffffu, p3, o);
            }

            const float g0 = 1.0f / (1.0f + __expf(-(p0 + bias)));
            const float g1 = 1.0f / (1.0f + __expf(-(p1 + bias)));
            const float g2 = 1.0f / (1.0f + __expf(-(p2 + bias)));
            const float g3 = 1.0f / (1.0f + __expf(-(p3 + bias)));

            // ---- branchless accumulate (single owner: no flush logic) ----
            acc.x += f0.x * g0 + f1.x * g1 + f2.x * g2 + f3.x * g3;
            acc.y += f0.y * g0 + f1.y * g1 + f2.y * g2 + f3.y * g3;
            acc.z += f0.z * g0 + f1.z * g1 + f2.z * g2 + f3.z * g3;
            acc.w += f0.w * g0 + f1.w * g1 + f2.w * g2 + f3.w * g3;

            if (!more) { r = rn; break; }
            f0 = f0n; f1 = f1n; f2 = f2n; f3 = f3n;
            r = rn;
        }
    }

    // ---- tail rows (0..3) ----
    for (; r < end; ++r) {
        const float4 f =
            reinterpret_cast<const float4*>(feats)[(size_t)r * (D_DIM / 4) + lane];
        float p = f.x * wv.x + f.y * wv.y + f.z * wv.z + f.w * wv.w;
#pragma unroll
        for (int o = 16; o > 0; o >>= 1) p += __shfl_xor_sync(0xffffffffu, p, o);
        const float g = 1.0f / (1.0f + __expf(-(p + bias)));
        acc.x += f.x * g;
        acc.y += f.y * g;
        acc.z += f.z * g;
        acc.w += f.w * g;
    }

    // ---- exclusive owner: single plain store (zeros for empty segments) ----
    *reinterpret_cast<float4*>(out + (size_t)s * D_DIM + lane * 4) = acc;
}

extern "C" void kernel_launch(void* const* d_in, const int* in_sizes, int n_in,
                              void* d_out, int out_size)
{
    const float* feats = (const float*)d_in[0];
    const int*   seg   = (const int*)d_in[1];
    const float* w     = (const float*)d_in[2];
    const float* b     = (const float*)d_in[3];
    float*       out   = (float*)d_out;

    const int N = in_sizes[1];            // rows
    const int B = out_size / D_DIM;       // segments (65536)

    const int groups = (N + 3) / 4;
    offs_kernel<<<(groups + 255) / 256, 256>>>(seg, N, B);

    // was_kernel with programmatic dependent launch: its g_offs-independent
    // prologue overlaps offs_kernel's tail; correctness guarded by
    // cudaGridDependencySynchronize() in the kernel.
    const int blocks = (B + WARPS - 1) / WARPS;

    cudaLaunchConfig_t cfg = {};
    cfg.gridDim  = dim3(blocks, 1, 1);
    cfg.blockDim = dim3(THREADS, 1, 1);
    cfg.dynamicSmemBytes = 0;
    cfg.stream = 0;
    cudaLaunchAttribute attrs[1];
    attrs[0].id = cudaLaunchAttributeProgrammaticStreamSerialization;
    attrs[0].val.programmaticStreamSerializationAllowed = 1;
    cfg.attrs = attrs;
    cfg.numAttrs = 1;

    cudaError_t e = cudaLaunchKernelEx(&cfg, was_kernel, feats, w, b, out, B);
    if (e != cudaSuccess) {
        // fallback: plain launch (serialized)
        was_kernel<<<blocks, THREADS>>>(feats, w, b, out, B);
    }
}

// round 12
// speedup vs baseline: 1.2519x; 1.0013x over previous
#include <cuda_runtime.h>
#include <cuda_bf16.h>

// WeightAndSum: out[s, :] = sum_{r in segment s} feats[r,:] * sigmoid(dot(feats[r,:], w) + b)
// N = 2,000,000 rows, D = 128, B = 65536 segments, segment_ids sorted ascending.
//
// Two-kernel plan, zero atomics, zero memset:
//  1) offs_kernel (vectorized int4, shuffle for prev): g_offs[b] = first row
//     of segment b, g_offs[B] = N, handling empty segments.
//  2) was_kernel (R6 loop shape — proven best): warp per segment, exclusive
//     ownership, branchless double-buffered 4-row pipeline, one float4 store
//     per lane per segment (empties store zeros). Sigmoid division uses
//     __fdividef (MUFU.RCP + mul) instead of IEEE FDIV — removes a ~15-instr
//     serial chain per row from the gate critical path (rel tolerance 1e-3,
//     we are at ~1e-7). Launched with PDL; THREADS=128 for finer block tail.

#define D_DIM 128
#define THREADS 128
#define WARPS (THREADS / 32)
#define MAX_B 65536

#define SIGMOID(t) __fdividef(1.0f, 1.0f + __expf(-(t)))

__device__ int g_offs[MAX_B + 1];

__global__ __launch_bounds__(256) void offs_kernel(
    const int* __restrict__ seg, int N, int B)
{
    const int i    = blockIdx.x * blockDim.x + threadIdx.x;
    const int base = i * 4;
    const int lane = threadIdx.x & 31;

    int ids[4] = {0, 0, 0, 0};
    const bool active = (base < N);
    if (active) {
        if (base + 4 <= N) {
            const int4 v = *reinterpret_cast<const int4*>(seg + base);
            ids[0] = v.x; ids[1] = v.y; ids[2] = v.z; ids[3] = v.w;
        } else {
#pragma unroll
            for (int k = 0; k < 4; ++k)
                ids[k] = (base + k < N) ? __ldg(seg + base + k) : 0;
        }
    }

    // prev = seg[base-1]: lane l-1 holds it as ids[3]; warp-edge lanes load it
    const int up = __shfl_up_sync(0xffffffffu, ids[3], 1);
    int prev;
    if (lane == 0)
        prev = (base == 0) ? -1 : __ldg(seg + base - 1);
    else
        prev = up;

    if (!active) return;

    int p = prev;
#pragma unroll
    for (int k = 0; k < 4; ++k) {
        if (base + k >= N) break;
        const int s = ids[k];
        for (int bb = p + 1; bb <= s; ++bb) g_offs[bb] = base + k;
        p = s;
        if (base + k == N - 1)
            for (int bb = s + 1; bb <= B; ++bb) g_offs[bb] = N;
    }
}

__global__ __launch_bounds__(THREADS) void was_kernel(
    const float* __restrict__ feats,
    const float* __restrict__ w,
    const float* __restrict__ b,
    float*       __restrict__ out,
    int B)
{
    const int wid  = threadIdx.x >> 5;
    const int lane = threadIdx.x & 31;
    const int s    = blockIdx.x * WARPS + wid;

    // setup that does NOT depend on g_offs — overlaps offs_kernel via PDL
    const float4 wv  = reinterpret_cast<const float4*>(w)[lane];
    const float bias = __ldg(b);

#if __CUDA_ARCH__ >= 900
    cudaGridDependencySynchronize();
#endif

    if (s >= B) return;

    const int start = __ldg(&g_offs[s]);
    const int end   = __ldg(&g_offs[s + 1]);

    float4 acc = make_float4(0.f, 0.f, 0.f, 0.f);

    int r = start;
    const int stop = start + ((end - start) & ~3);  // full 4-row groups

    if (r < stop) {
        // ---- prologue: load group 0 ----
        const float4* base =
            reinterpret_cast<const float4*>(feats) + (size_t)r * (D_DIM / 4) + lane;
        float4 f0 = __ldcs(base);
        float4 f1 = __ldcs(base + (D_DIM / 4));
        float4 f2 = __ldcs(base + 2 * (D_DIM / 4));
        float4 f3 = __ldcs(base + 3 * (D_DIM / 4));

        for (;;) {
            const int rn    = r + 4;
            const bool more = (rn < stop);

            // ---- prefetch next group before current chain ----
            float4 f0n, f1n, f2n, f3n;
            if (more) {
                const float4* bn =
                    reinterpret_cast<const float4*>(feats) + (size_t)rn * (D_DIM / 4) + lane;
                f0n = __ldcs(bn);
                f1n = __ldcs(bn + (D_DIM / 4));
                f2n = __ldcs(bn + 2 * (D_DIM / 4));
                f3n = __ldcs(bn + 3 * (D_DIM / 4));
            }

            // ---- 4 per-lane partial dots, 4 parallel butterflies ----
            float p0 = f0.x * wv.x + f0.y * wv.y + f0.z * wv.z + f0.w * wv.w;
            float p1 = f1.x * wv.x + f1.y * wv.y + f1.z * wv.z + f1.w * wv.w;
            float p2 = f2.x * wv.x + f2.y * wv.y + f2.z * wv.z + f2.w * wv.w;
            float p3 = f3.x * wv.x + f3.y * wv.y + f3.z * wv.z + f3.w * wv.w;

#pragma unroll
            for (int o = 16; o > 0; o >>= 1) {
                p0 += __shfl_xor_sync(0xffffffffu, p0, o);
                p1 += __shfl_xor_sync(0xffffffffu, p1, o);
                p2 += __shfl_xor_sync(0xffffffffu, p2, o);
                p3 += __shfl_xor_sync(0xffffffffu, p3, o);
            }

            const float g0 = SIGMOID(p0 + bias);
            const float g1 = SIGMOID(p1 + bias);
            const float g2 = SIGMOID(p2 + bias);
            const float g3 = SIGMOID(p3 + bias);

            // ---- branchless accumulate (single owner: no flush logic) ----
            acc.x += f0.x * g0 + f1.x * g1 + f2.x * g2 + f3.x * g3;
            acc.y += f0.y * g0 + f1.y * g1 + f2.y * g2 + f3.y * g3;
            acc.z += f0.z * g0 + f1.z * g1 + f2.z * g2 + f3.z * g3;
            acc.w += f0.w * g0 + f1.w * g1 + f2.w * g2 + f3.w * g3;

            if (!more) { r = rn; break; }
            f0 = f0n; f1 = f1n; f2 = f2n; f3 = f3n;
            r = rn;
        }
    }

    // ---- tail rows (0..3) ----
    for (; r < end; ++r) {
        const float4 f =
            reinterpret_cast<const float4*>(feats)[(size_t)r * (D_DIM / 4) + lane];
        float p = f.x * wv.x + f.y * wv.y + f.z * wv.z + f.w * wv.w;
#pragma unroll
        for (int o = 16; o > 0; o >>= 1) p += __shfl_xor_sync(0xffffffffu, p, o);
        const float g = SIGMOID(p + bias);
        acc.x += f.x * g;
        acc.y += f.y * g;
        acc.z += f.z * g;
        acc.w += f.w * g;
    }

    // ---- exclusive owner: single plain store (zeros for empty segments) ----
    *reinterpret_cast<float4*>(out + (size_t)s * D_DIM + lane * 4) = acc;
}

extern "C" void kernel_launch(void* const* d_in, const int* in_sizes, int n_in,
                              void* d_out, int out_size)
{
    const float* feats = (const float*)d_in[0];
    const int*   seg   = (const int*)d_in[1];
    const float* w     = (const float*)d_in[2];
    const float* b     = (const float*)d_in[3];
    float*       out   = (float*)d_out;

    const int N = in_sizes[1];            // rows
    const int B = out_size / D_DIM;       // segments (65536)

    const int groups = (N + 3) / 4;
    offs_kernel<<<(groups + 255) / 256, 256>>>(seg, N, B);

    // was_kernel with programmatic dependent launch: its g_offs-independent
    // prologue overlaps offs_kernel's tail; correctness guarded by
    // cudaGridDependencySynchronize() in the kernel.
    const int blocks = (B + WARPS - 1) / WARPS;

    cudaLaunchConfig_t cfg = {};
    cfg.gridDim  = dim3(blocks, 1, 1);
    cfg.blockDim = dim3(THREADS, 1, 1);
    cfg.dynamicSmemBytes = 0;
    cfg.stream = 0;
    cudaLaunchAttribute attrs[1];
    attrs[0].id = cudaLaunchAttributeProgrammaticStreamSerialization;
    attrs[0].val.programmaticStreamSerializationAllowed = 1;
    cfg.attrs = attrs;
    cfg.numAttrs = 1;

    cudaError_t e = cudaLaunchKernelEx(&cfg, was_kernel, feats, w, b, out, B);
    if (e != cudaSuccess) {
        // fallback: plain launch (serialized)
        was_kernel<<<blocks, THREADS>>>(feats, w, b, out, B);
    }
}